// round 14
// baseline (speedup 1.0000x reference)
#include <cuda_runtime.h>
#include <cuda_fp16.h>
#include <math.h>
#include <stdint.h>

// Problem constants
#define BROWS 16384
#define D     1024

// Output layout: retrieved (B*D) | loss (1) | new_weight (D*D) | new_momentum (D*D) | gates (3)
#define RET_OFF   0
#define LOSS_OFF  (BROWS * D)
#define W_OFF     (LOSS_OFF + 1)              // odd -> scalar stores only
#define NM_OFF    (W_OFF + D * D)             // odd -> scalar stores only
#define GATES_OFF (NM_OFF + D * D)

#define MEM_MAX_NORM 5.0f
#define TTT_LR 0.005f
#define TWO_OVER_N (2.0f / (float)(BROWS * D))

#define NZ 4   // gemm2 split-B slices (proven best)

// ---------------- device scratch (static, no runtime allocation) ----------------
__device__ float g_kagg_part[128][D];
__device__ float g_scalars[8];        // 0:alpha 1:eta 2:theta 4:scale_m 5:scale_w
__device__ float g_loss_part[1024];
__device__ float g_grad_part[NZ][D * D];  // split-B partials for GEMM2 (16 MB)
__device__ float g_norm_part[2][256];
__device__ volatile int g_ctr[2];         // 0..255 counting; -1 = scale ready
__device__ __half g_k_h[BROWS * D];        // fp16 K, row-major [b][c] (32 MB)
__device__ __half g_w_h[D * D];            // fp16 W, row-major [n][k] (2 MB)
__device__ __half g_kT_h[D * BROWS];       // fp16 K^T [c][b] (32 MB)
__device__ __half g_diffT_h[D * BROWS];    // fp16 (retrieved-V)^T [i][b] (32 MB)

// ================= PTX helpers (family-portable, sm_80+) =================
__device__ __forceinline__ uint32_t pack_half(float a, float b) {
    __half2 h = __floats2half2_rn(a, b);
    return *(uint32_t*)&h;
}
__device__ __forceinline__ void mma_f16(float& c0, float& c1, float& c2, float& c3,
                                        uint32_t a0, uint32_t a1, uint32_t a2, uint32_t a3,
                                        uint32_t b0, uint32_t b1) {
    asm volatile(
        "mma.sync.aligned.m16n8k16.row.col.f32.f16.f16.f32 "
        "{%0,%1,%2,%3}, {%4,%5,%6,%7}, {%8,%9}, {%0,%1,%2,%3};"
        : "+f"(c0), "+f"(c1), "+f"(c2), "+f"(c3)
        : "r"(a0), "r"(a1), "r"(a2), "r"(a3), "r"(b0), "r"(b1));
}
__device__ __forceinline__ void ldsm_x4(uint32_t& r0, uint32_t& r1, uint32_t& r2, uint32_t& r3,
                                        uint32_t addr) {
    asm volatile("ldmatrix.sync.aligned.m8n8.x4.shared.b16 {%0,%1,%2,%3}, [%4];"
                 : "=r"(r0), "=r"(r1), "=r"(r2), "=r"(r3) : "r"(addr));
}
__device__ __forceinline__ uint32_t smem_u32(const void* p) {
    uint32_t a;
    asm("{ .reg .u64 t; cvta.to.shared.u64 t, %1; cvt.u32.u64 %0, t; }" : "=r"(a) : "l"(p));
    return a;
}
__device__ __forceinline__ void cp16(uint32_t dst, const void* src) {
    asm volatile("cp.async.cg.shared.global [%0], [%1], 16;" :: "r"(dst), "l"(src));
}
#define CP_COMMIT() asm volatile("cp.async.commit_group;" ::: "memory")
#define CP_WAIT1()  asm volatile("cp.async.wait_group 1;" ::: "memory")
#define CP_WAIT0()  asm volatile("cp.async.wait_group 0;" ::: "memory")

// K-chunk 64: stage = A(128x64 half = 16KB) + B(16KB) = 32KB = 8192 words
#define STAGE_WORDS 8192
#define B_OFF_WORDS 4096

// ---------------- colsum + fp16(K) + fp16 K^T + fp16(W) (fused prep) ----------------
__global__ __launch_bounds__(256) void colsum_prep_kernel(const float* __restrict__ K,
                                                          const float* __restrict__ W) {
    if (blockIdx.y == 128) {   // W conversion blocks
        int base = (blockIdx.x * 256 + threadIdx.x) * 2;
        #pragma unroll
        for (int it = 0; it < 256; ++it) {
            int e = base + it * 4096;
            float2 w2 = *(const float2*)(W + e);
            *(uint32_t*)(&g_w_h[e]) = pack_half(w2.x, w2.y);
        }
        return;
    }
    __shared__ uint32_t st[128 * 64];
    __shared__ float red2[256];
    const int t  = threadIdx.x;
    const int cl = t & 127, rq = t >> 7;
    const int c  = blockIdx.x * 128 + cl;
    const int r0 = blockIdx.y * 128;

    float s = 0.f, prev = 0.f;
    #pragma unroll 4
    for (int i = 0; i < 64; ++i) {
        int r = r0 + rq * 64 + i;
        float kv = K[(size_t)r * D + c];
        s += kv;
        g_k_h[(size_t)r * D + c] = __float2half_rn(kv);
        if (i & 1) {
            int r2 = rq * 32 + (i >> 1);
            st[cl * 64 + (r2 ^ (cl & 31))] = pack_half(prev, kv);
        } else prev = kv;
    }
    red2[t] = s;
    __syncthreads();
    if (t < 128) g_kagg_part[blockIdx.y][blockIdx.x * 128 + t] = red2[t] + red2[t + 128];

    uint32_t* kTw = (uint32_t*)g_kT_h;
    size_t dstbase = ((size_t)(blockIdx.x * 128 + cl) * BROWS + r0) / 2 + rq * 32;
    #pragma unroll
    for (int q4 = 0; q4 < 32; q4 += 4) {
        uint4 vv;
        vv.x = st[cl * 64 + ((rq * 32 + q4 + 0) ^ (cl & 31))];
        vv.y = st[cl * 64 + ((rq * 32 + q4 + 1) ^ (cl & 31))];
        vv.z = st[cl * 64 + ((rq * 32 + q4 + 2) ^ (cl & 31))];
        vv.w = st[cl * 64 + ((rq * 32 + q4 + 3) ^ (cl & 31))];
        *(uint4*)(kTw + dstbase + q4) = vv;
    }
}

// ======= shared GEMM body pieces (4 warps, 64x64 warp tile, k64 chunks) =======
#define FRAG_SETUP()                                              \
    const int laneRowA = (lane & 7) | (lane & 8);                 \
    const int selA = lane >> 4;                                   \
    const int laneRowB = (lane & 7) | ((lane & 16) >> 1);         \
    const int selB = (lane >> 3) & 1;                             \
    uint32_t offA[4], swA4[4];                                    \
    _Pragma("unroll")                                             \
    for (int mt = 0; mt < 4; ++mt) {                              \
        int row = wm + mt * 16 + laneRowA;                        \
        offA[mt] = row * 128;                                     \
        swA4[mt] = row & 7;                                       \
    }                                                             \
    uint32_t offB[4], swB4[4];                                    \
    _Pragma("unroll")                                             \
    for (int np = 0; np < 4; ++np) {                              \
        int row = wn + np * 16 + laneRowB;                        \
        offB[np] = row * 128;                                     \
        swB4[np] = row & 7;                                       \
    }

#define CHUNK_COMPUTE(abase, bbase)                                                   \
    _Pragma("unroll")                                                                 \
    for (int ks = 0; ks < 4; ++ks) {                                                  \
        const int g0 = ks * 2;                                                        \
        uint32_t a[4][4], b[4][4];                                                    \
        _Pragma("unroll")                                                             \
        for (int mt = 0; mt < 4; ++mt)                                                \
            ldsm_x4(a[mt][0], a[mt][1], a[mt][2], a[mt][3],                           \
                    (abase) + offA[mt] + ((((uint32_t)(g0 + selA)) ^ swA4[mt]) << 4));\
        _Pragma("unroll")                                                             \
        for (int np = 0; np < 4; ++np)                                                \
            ldsm_x4(b[np][0], b[np][1], b[np][2], b[np][3],                           \
                    (bbase) + offB[np] + ((((uint32_t)(g0 + selB)) ^ swB4[np]) << 4));\
        _Pragma("unroll")                                                             \
        for (int mt = 0; mt < 4; ++mt)                                                \
            _Pragma("unroll")                                                         \
            for (int nt = 0; nt < 8; ++nt) {                                          \
                const int np = nt >> 1, lo = (nt & 1) * 2;                            \
                mma_f16(acc[mt][nt][0], acc[mt][nt][1], acc[mt][nt][2], acc[mt][nt][3],\
                        a[mt][0], a[mt][1], a[mt][2], a[mt][3], b[np][lo], b[np][lo + 1]);\
            }                                                                         \
    }

#define STAGE_CHUNK(stagebase, srcA, srcB)                                            \
    _Pragma("unroll")                                                                 \
    for (int it = 0; it < 8; ++it) {                                                  \
        int row = it * 16 + srow;                                                     \
        uint32_t wo = (uint32_t)(row * 32 + ((sg ^ (row & 7)) << 2));                 \
        cp16((stagebase) + wo * 4, (srcA) + (size_t)row * srcStrideA);                \
        cp16((stagebase) + (B_OFF_WORDS + wo) * 4, (srcB) + (size_t)row * srcStrideB);\
    }

// ---------------- GEMM1 (fp16, 64x64 warp tile): retrieved = K @ W^T ----------------
// blockIdx.y == 128 row: fused kagg+gates (1 active CTA) + counter reset.
__global__ __launch_bounds__(128, 2) void gemm1_f16_kernel(
    const float* __restrict__ V, const float* __restrict__ GW,
    const float* __restrict__ GB, float* __restrict__ out) {
    extern __shared__ uint32_t sm1[];
    __shared__ float wred[4];
    const int tid = threadIdx.x;

    if (blockIdx.y == 128) {     // fused kagg + gates
        if (blockIdx.x != 0) return;
        float* kag = (float*)sm1;          // 1024 floats
        float* red = kag + 1024;           // 128 floats
        if (tid == 0) { g_ctr[0] = 0; g_ctr[1] = 0; }
        for (int col = tid; col < D; col += 128) {
            float s = 0.f;
            #pragma unroll 8
            for (int p = 0; p < 128; ++p) s += g_kagg_part[p][col];
            kag[col] = s * (1.0f / (float)BROWS);
        }
        __syncthreads();
        for (int g = 0; g < 3; ++g) {
            float pr = 0.f;
            for (int col = tid; col < D; col += 128) pr += kag[col] * GW[g * D + col];
            red[tid] = pr;
            __syncthreads();
            for (int s = 64; s > 0; s >>= 1) {
                if (tid < s) red[tid] += red[tid + s];
                __syncthreads();
            }
            if (tid == 0) {
                float z  = red[0] + GB[g];
                float sg = 1.0f / (1.0f + expf(-z));
                g_scalars[g] = sg;
                out[GATES_OFF + g] = sg;
            }
            __syncthreads();
        }
        return;
    }

    const uint32_t sb = smem_u32(sm1);
    const int warp = tid >> 5, lane = tid & 31;
    const int t4 = lane >> 2, tm4 = lane & 3;
    const int n0 = blockIdx.x * 128;
    const int m0 = blockIdx.y * 128;
    const int wm = (warp >> 1) * 64;
    const int wn = (warp & 1) * 64;

    float acc[4][8][4];
    #pragma unroll
    for (int i = 0; i < 4; ++i)
        #pragma unroll
        for (int j = 0; j < 8; ++j)
            #pragma unroll
            for (int r = 0; r < 4; ++r) acc[i][j][r] = 0.f;

    FRAG_SETUP();

    const int srow = tid >> 3, sg = tid & 7;
    const size_t srcStrideA = D, srcStrideB = D;
    const __half* gA = g_k_h + (size_t)m0 * D + sg * 8;
    const __half* gB = g_w_h + (size_t)n0 * D + sg * 8;

    #pragma unroll
    for (int s = 0; s < 2; ++s) {
        STAGE_CHUNK(sb + s * (STAGE_WORDS * 4), gA + s * 64, gB + s * 64);
        CP_COMMIT();
    }

    const int NCH = D / 64;   // 16 chunks
    for (int c = 0; c < NCH; ++c) {
        const int buf = c % 3;
        CP_WAIT1();
        __syncthreads();
        if (c + 2 < NCH) {
            const int nb = (c + 2) % 3;
            STAGE_CHUNK(sb + nb * (STAGE_WORDS * 4), gA + (c + 2) * 64, gB + (c + 2) * 64);
        }
        CP_COMMIT();

        const uint32_t abase = sb + buf * (STAGE_WORDS * 4);
        const uint32_t bbase = abase + B_OFF_WORDS * 4;
        CHUNK_COMPUTE(abase, bbase);
    }

    // ---- Epilogue ----
    CP_WAIT0();
    __syncthreads();   // pipeline smem free; reuse for diff repack

    float lsum = 0.f;
    #pragma unroll
    for (int mt = 0; mt < 4; ++mt) {
        #pragma unroll
        for (int nt = 0; nt < 8; ++nt) {
            int r   = wm + mt * 16 + t4;
            int ccl = wn + nt * 8 + 2 * tm4;
            int rg = m0 + r, cg = n0 + ccl;
            size_t e0 = (size_t)rg * D + cg;
            size_t e1 = (size_t)(rg + 8) * D + cg;
            float2 v0 = *(const float2*)(V + e0);
            float2 v1 = *(const float2*)(V + e1);
            float2 c0 = make_float2(acc[mt][nt][0], acc[mt][nt][1]);
            float2 c1 = make_float2(acc[mt][nt][2], acc[mt][nt][3]);
            *(float2*)(out + RET_OFF + e0) = c0;
            *(float2*)(out + RET_OFF + e1) = c1;
            float d0 = c0.x - v0.x, d1 = c0.y - v0.y;
            float d2 = c1.x - v1.x, d3 = c1.y - v1.y;
            int wrow = ccl >> 1;
            sm1[wrow * 136 + r]     = pack_half(d0, d1);
            sm1[wrow * 136 + r + 8] = pack_half(d2, d3);
            lsum += d0 * d0 + d1 * d1 + d2 * d2 + d3 * d3;
        }
    }
    #pragma unroll
    for (int o = 16; o > 0; o >>= 1) lsum += __shfl_xor_sync(0xffffffffu, lsum, o);
    if (lane == 0) wred[warp] = lsum;
    __syncthreads();

    for (int row = warp; row < 128; row += 4) {
        uint4 w = *(uint4*)&sm1[(row >> 1) * 136 + lane * 4];
        uint32_t sel = (row & 1) ? 0x7632u : 0x5410u;
        uint32_t lo = __byte_perm(w.x, w.y, sel);
        uint32_t hi = __byte_perm(w.z, w.w, sel);
        *(uint2*)&g_diffT_h[(size_t)(n0 + row) * BROWS + m0 + lane * 4] = make_uint2(lo, hi);
    }

    if (tid == 0)
        g_loss_part[blockIdx.y * 8 + blockIdx.x] = wred[0] + wred[1] + wred[2] + wred[3];
}

// ---------------- GEMM2 (fp16, 64x64 warp tile): grad_part[z] = diffT @ kT^T ----------------
__global__ __launch_bounds__(128, 2) void gemm2_f16_kernel() {
    extern __shared__ uint32_t sm2[];
    const uint32_t sb = smem_u32(sm2);

    const int tid = threadIdx.x;
    const int warp = tid >> 5, lane = tid & 31;
    const int t4 = lane >> 2, tm4 = lane & 3;
    const int j0 = blockIdx.x * 128;
    const int i0 = blockIdx.y * 128;
    const int z  = blockIdx.z;
    const int b0z = z * (BROWS / NZ);
    const int wm = (warp >> 1) * 64;   // i
    const int wn = (warp & 1) * 64;    // j

    float acc[4][8][4];
    #pragma unroll
    for (int i = 0; i < 4; ++i)
        #pragma unroll
        for (int j = 0; j < 8; ++j)
            #pragma unroll
            for (int r = 0; r < 4; ++r) acc[i][j][r] = 0.f;

    FRAG_SETUP();

    const int srow = tid >> 3, sg = tid & 7;
    const size_t srcStrideA = BROWS, srcStrideB = BROWS;
    const __half* gA = g_diffT_h + (size_t)i0 * BROWS + b0z + sg * 8;
    const __half* gB = g_kT_h    + (size_t)j0 * BROWS + b0z + sg * 8;

    #pragma unroll
    for (int s = 0; s < 2; ++s) {
        STAGE_CHUNK(sb + s * (STAGE_WORDS * 4), gA + s * 64, gB + s * 64);
        CP_COMMIT();
    }

    const int NCH = (BROWS / NZ) / 64;   // 64 chunks
    for (int c = 0; c < NCH; ++c) {
        const int buf = c % 3;
        CP_WAIT1();
        __syncthreads();
        if (c + 2 < NCH) {
            const int nb = (c + 2) % 3;
            STAGE_CHUNK(sb + nb * (STAGE_WORDS * 4), gA + (c + 2) * 64, gB + (c + 2) * 64);
        }
        CP_COMMIT();

        const uint32_t abase = sb + buf * (STAGE_WORDS * 4);
        const uint32_t bbase = abase + B_OFF_WORDS * 4;
        CHUNK_COMPUTE(abase, bbase);
    }

    float* gp = g_grad_part[z];
    #pragma unroll
    for (int mt = 0; mt < 4; ++mt) {
        #pragma unroll
        for (int nt = 0; nt < 8; ++nt) {
            int r  = i0 + wm + mt * 16 + t4;
            int cc = j0 + wn + nt * 8 + 2 * tm4;
            *(float2*)(gp + (size_t)r * D + cc)       = make_float2(acc[mt][nt][0], acc[mt][nt][1]);
            *(float2*)(gp + (size_t)(r + 8) * D + cc) = make_float2(acc[mt][nt][2], acc[mt][nt][3]);
        }
    }
}

// ---------------- fused update: loss + momentum + norm + weight + norm + final ----------------
__global__ __launch_bounds__(256) void fused_update_kernel(
    const float* __restrict__ MOM, const float* __restrict__ MW, float* __restrict__ out) {
    __shared__ float red[256];
    __shared__ int amLast;
    const int tid = threadIdx.x;
    const int t = blockIdx.x * 256 + tid;

    if (blockIdx.x == 0) {   // loss reduce
        float ls = g_loss_part[tid] + g_loss_part[tid + 256] +
                   g_loss_part[tid + 512] + g_loss_part[tid + 768];
        red[tid] = ls;
        __syncthreads();
        for (int s = 128; s > 0; s >>= 1) {
            if (tid < s) red[tid] += red[tid + s];
            __syncthreads();
        }
        if (tid == 0) out[LOSS_OFF] = red[0] / (float)(BROWS * D);
        __syncthreads();
    }

    const float eta = g_scalars[1], theta = g_scalars[2];
    const float lr_th = TTT_LR * theta;
    const float one_m_a = 1.0f - g_scalars[0];

    // Phase 1: nm in registers + norm partial
    float nm[16];
    float nsum = 0.f;
    #pragma unroll
    for (int it = 0; it < 16; ++it) {
        int e = t + it * 65536;
        float g = 0.f;
        #pragma unroll
        for (int z = 0; z < NZ; ++z) g += g_grad_part[z][e];
        g *= TWO_OVER_N;
        float gc = fminf(1.0f, fmaxf(-1.0f, g));
        nm[it] = eta * MOM[e] - lr_th * gc;
        nsum += nm[it] * nm[it];
    }
    red[tid] = nsum;
    __syncthreads();
    for (int s = 128; s > 0; s >>= 1) {
        if (tid < s) red[tid] += red[tid + s];
        __syncthreads();
    }
    if (tid == 0) {
        g_norm_part[0][blockIdx.x] = red[0];
        __threadfence();
        amLast = (atomicAdd((int*)&g_ctr[0], 1) == 255);
    }
    __syncthreads();
    if (amLast) {
        red[tid] = g_norm_part[0][tid];
        __syncthreads();
        for (int s = 128; s > 0; s >>= 1) {
            if (tid < s) red[tid] += red[tid + s];
            __syncthreads();
        }
        if (tid == 0) {
            float n = sqrtf(red[0]);
            g_scalars[4] = (n > MEM_MAX_NORM) ? (MEM_MAX_NORM / (n + 1e-8f)) : 1.0f;
            __threadfence();
            g_ctr[0] = -1;
        }
    }
    if (tid == 0) { while (g_ctr[0] >= 0) { } }
    __syncthreads();
    __threadfence();
    const float sm_ = g_scalars[4];

    // Phase 2: nm output, w in registers + norm partial
    float w[16];
    float wsum = 0.f;
    #pragma unroll
    for (int it = 0; it < 16; ++it) {
        int e = t + it * 65536;
        float nmv = nm[it] * sm_;
        out[NM_OFF + e] = nmv;
        w[it] = one_m_a * MW[e] + nmv;
        wsum += w[it] * w[it];
    }
    red[tid] = wsum;
    __syncthreads();
    for (int s = 128; s > 0; s >>= 1) {
        if (tid < s) red[tid] += red[tid + s];
        __syncthreads();
    }
    if (tid == 0) {
        g_norm_part[1][blockIdx.x] = red[0];
        __threadfence();
        amLast = (atomicAdd((int*)&g_ctr[1], 1) == 255);
    }
    __syncthreads();
    if (amLast) {
        red[tid] = g_norm_part[1][tid];
        __syncthreads();
        for (int s = 128; s > 0; s >>= 1) {
            if (tid < s) red[tid] += red[tid + s];
            __syncthreads();
        }
        if (tid == 0) {
            float n = sqrtf(red[0]);
            g_scalars[5] = (n > MEM_MAX_NORM) ? (MEM_MAX_NORM / (n + 1e-8f)) : 1.0f;
            __threadfence();
            g_ctr[1] = -1;
        }
    }
    if (tid == 0) { while (g_ctr[1] >= 0) { } }
    __syncthreads();
    __threadfence();
    const float sw = g_scalars[5];

    #pragma unroll
    for (int it = 0; it < 16; ++it) {
        int e = t + it * 65536;
        out[W_OFF + e] = w[it] * sw;
    }
}

// ---------------- launch ----------------
extern "C" void kernel_launch(void* const* d_in, const int* in_sizes, int n_in,
                              void* d_out, int out_size) {
    const float* k    = (const float*)d_in[0];
    const float* v    = (const float*)d_in[1];
    const float* memw = (const float*)d_in[2];
    const float* gw   = (const float*)d_in[3];
    const float* gb   = (const float*)d_in[4];
    const float* mom  = (const float*)d_in[5];
    float* out = (float*)d_out;

    const int g_smem = 3 * STAGE_WORDS * 4;   // 98304
    cudaFuncSetAttribute(gemm1_f16_kernel, cudaFuncAttributeMaxDynamicSharedMemorySize, g_smem);
    cudaFuncSetAttribute(gemm2_f16_kernel, cudaFuncAttributeMaxDynamicSharedMemorySize, g_smem);

    colsum_prep_kernel<<<dim3(8, 129), 256>>>(k, memw);
    gemm1_f16_kernel<<<dim3(8, 129), 128, g_smem>>>(v, gw, gb, out);   // +gates grid row
    gemm2_f16_kernel<<<dim3(8, 8, NZ), 128, g_smem>>>();
    fused_update_kernel<<<256, 256>>>(mom, memw, out);
}

// round 16
// speedup vs baseline: 1.1586x; 1.1586x over previous
#include <cuda_runtime.h>
#include <cuda_fp16.h>
#include <math.h>
#include <stdint.h>

// Problem constants
#define BROWS 16384
#define D     1024

// Output layout: retrieved (B*D) | loss (1) | new_weight (D*D) | new_momentum (D*D) | gates (3)
#define RET_OFF   0
#define LOSS_OFF  (BROWS * D)
#define W_OFF     (LOSS_OFF + 1)              // odd -> scalar stores only
#define NM_OFF    (W_OFF + D * D)             // odd -> scalar stores only
#define GATES_OFF (NM_OFF + D * D)

#define MEM_MAX_NORM 5.0f
#define TTT_LR 0.005f
#define TWO_OVER_N (2.0f / (float)(BROWS * D))

#define NZ 4   // gemm2 split-B slices (proven best)

// ---------------- device scratch (static, no runtime allocation) ----------------
__device__ float g_kagg_part[128][D];
__device__ float g_scalars[8];        // 0:alpha 1:eta 2:theta 4:scale_m 5:scale_w
__device__ float g_loss_part[1024];
__device__ float g_grad_part[NZ][D * D];  // split-B partials for GEMM2 (16 MB)
__device__ float g_norm_part[2][256];
__device__ volatile int g_ctr[2];         // 0..255 counting; -1 = scale ready
__device__ __half g_k_h[BROWS * D];        // fp16 K, row-major [b][c] (32 MB)
__device__ __half g_w_h[D * D];            // fp16 W, row-major [n][k] (2 MB)
__device__ __half g_kT_h[D * BROWS];       // fp16 K^T [c][b] (32 MB)
__device__ __half g_diffT_h[D * BROWS];    // fp16 (retrieved-V)^T [i][b] (32 MB)

// ================= PTX helpers (family-portable, sm_80+) =================
__device__ __forceinline__ uint32_t pack_half(float a, float b) {
    __half2 h = __floats2half2_rn(a, b);
    return *(uint32_t*)&h;
}
__device__ __forceinline__ void mma_f16(float& c0, float& c1, float& c2, float& c3,
                                        uint32_t a0, uint32_t a1, uint32_t a2, uint32_t a3,
                                        uint32_t b0, uint32_t b1) {
    asm volatile(
        "mma.sync.aligned.m16n8k16.row.col.f32.f16.f16.f32 "
        "{%0,%1,%2,%3}, {%4,%5,%6,%7}, {%8,%9}, {%0,%1,%2,%3};"
        : "+f"(c0), "+f"(c1), "+f"(c2), "+f"(c3)
        : "r"(a0), "r"(a1), "r"(a2), "r"(a3), "r"(b0), "r"(b1));
}
__device__ __forceinline__ void ldsm_x4(uint32_t& r0, uint32_t& r1, uint32_t& r2, uint32_t& r3,
                                        uint32_t addr) {
    asm volatile("ldmatrix.sync.aligned.m8n8.x4.shared.b16 {%0,%1,%2,%3}, [%4];"
                 : "=r"(r0), "=r"(r1), "=r"(r2), "=r"(r3) : "r"(addr));
}
__device__ __forceinline__ uint32_t smem_u32(const void* p) {
    uint32_t a;
    asm("{ .reg .u64 t; cvta.to.shared.u64 t, %1; cvt.u32.u64 %0, t; }" : "=r"(a) : "l"(p));
    return a;
}
__device__ __forceinline__ void cp16(uint32_t dst, const void* src) {
    asm volatile("cp.async.cg.shared.global [%0], [%1], 16;" :: "r"(dst), "l"(src));
}
#define CP_COMMIT() asm volatile("cp.async.commit_group;" ::: "memory")
#define CP_WAIT1()  asm volatile("cp.async.wait_group 1;" ::: "memory")
#define CP_WAIT0()  asm volatile("cp.async.wait_group 0;" ::: "memory")

// K-chunk 64: stage = A(128x64 half = 16KB) + B(16KB) = 32KB = 8192 words
#define STAGE_WORDS 8192
#define B_OFF_WORDS 4096

// ---------------- colsum + fp16(K) + fp16 K^T + fp16(W) (fused prep) ----------------
__global__ __launch_bounds__(256) void colsum_prep_kernel(const float* __restrict__ K,
                                                          const float* __restrict__ W) {
    if (blockIdx.y == 128) {   // W conversion blocks
        int base = (blockIdx.x * 256 + threadIdx.x) * 2;
        #pragma unroll
        for (int it = 0; it < 256; ++it) {
            int e = base + it * 4096;
            float2 w2 = *(const float2*)(W + e);
            *(uint32_t*)(&g_w_h[e]) = pack_half(w2.x, w2.y);
        }
        return;
    }
    __shared__ uint32_t st[128 * 64];
    __shared__ float red2[256];
    const int t  = threadIdx.x;
    const int cl = t & 127, rq = t >> 7;
    const int c  = blockIdx.x * 128 + cl;
    const int r0 = blockIdx.y * 128;

    float s = 0.f, prev = 0.f;
    #pragma unroll 8
    for (int i = 0; i < 64; ++i) {
        int r = r0 + rq * 64 + i;
        float kv = K[(size_t)r * D + c];
        s += kv;
        g_k_h[(size_t)r * D + c] = __float2half_rn(kv);
        if (i & 1) {
            int r2 = rq * 32 + (i >> 1);
            st[cl * 64 + (r2 ^ (cl & 31))] = pack_half(prev, kv);
        } else prev = kv;
    }
    red2[t] = s;
    __syncthreads();
    if (t < 128) g_kagg_part[blockIdx.y][blockIdx.x * 128 + t] = red2[t] + red2[t + 128];

    uint32_t* kTw = (uint32_t*)g_kT_h;
    size_t dstbase = ((size_t)(blockIdx.x * 128 + cl) * BROWS + r0) / 2 + rq * 32;
    #pragma unroll
    for (int q4 = 0; q4 < 32; q4 += 4) {
        uint4 vv;
        vv.x = st[cl * 64 + ((rq * 32 + q4 + 0) ^ (cl & 31))];
        vv.y = st[cl * 64 + ((rq * 32 + q4 + 1) ^ (cl & 31))];
        vv.z = st[cl * 64 + ((rq * 32 + q4 + 2) ^ (cl & 31))];
        vv.w = st[cl * 64 + ((rq * 32 + q4 + 3) ^ (cl & 31))];
        *(uint4*)(kTw + dstbase + q4) = vv;
    }
}

// ---------------- fused kagg + gates (+ counter reset for graph replay) ----------------
__global__ void kagg_gates_kernel(const float* __restrict__ GW, const float* __restrict__ GB,
                                  float* __restrict__ out) {
    __shared__ float red[1024];
    __shared__ float kag[1024];
    int t = threadIdx.x;
    if (t == 0) { g_ctr[0] = 0; g_ctr[1] = 0; }
    float s = 0.f;
    #pragma unroll 8
    for (int p = 0; p < 128; ++p) s += g_kagg_part[p][t];
    kag[t] = s * (1.0f / (float)BROWS);
    __syncthreads();
    for (int g = 0; g < 3; ++g) {
        red[t] = kag[t] * GW[g * D + t];
        __syncthreads();
        for (int st = 512; st > 0; st >>= 1) {
            if (t < st) red[t] += red[t + st];
            __syncthreads();
        }
        if (t == 0) {
            float z  = red[0] + GB[g];
            float sg = 1.0f / (1.0f + expf(-z));
            g_scalars[g] = sg;
            out[GATES_OFF + g] = sg;
        }
        __syncthreads();
    }
}

// ======= shared GEMM body pieces (4 warps, 64x64 warp tile, k64 chunks) =======
#define FRAG_SETUP()                                              \
    const int laneRowA = (lane & 7) | (lane & 8);                 \
    const int selA = lane >> 4;                                   \
    const int laneRowB = (lane & 7) | ((lane & 16) >> 1);         \
    const int selB = (lane >> 3) & 1;                             \
    uint32_t offA[4], swA4[4];                                    \
    _Pragma("unroll")                                             \
    for (int mt = 0; mt < 4; ++mt) {                              \
        int row = wm + mt * 16 + laneRowA;                        \
        offA[mt] = row * 128;                                     \
        swA4[mt] = row & 7;                                       \
    }                                                             \
    uint32_t offB[4], swB4[4];                                    \
    _Pragma("unroll")                                             \
    for (int np = 0; np < 4; ++np) {                              \
        int row = wn + np * 16 + laneRowB;                        \
        offB[np] = row * 128;                                     \
        swB4[np] = row & 7;                                       \
    }

#define CHUNK_COMPUTE(abase, bbase)                                                   \
    _Pragma("unroll")                                                                 \
    for (int ks = 0; ks < 4; ++ks) {                                                  \
        const int g0 = ks * 2;                                                        \
        uint32_t a[4][4], b[4][4];                                                    \
        _Pragma("unroll")                                                             \
        for (int mt = 0; mt < 4; ++mt)                                                \
            ldsm_x4(a[mt][0], a[mt][1], a[mt][2], a[mt][3],                           \
                    (abase) + offA[mt] + ((((uint32_t)(g0 + selA)) ^ swA4[mt]) << 4));\
        _Pragma("unroll")                                                             \
        for (int np = 0; np < 4; ++np)                                                \
            ldsm_x4(b[np][0], b[np][1], b[np][2], b[np][3],                           \
                    (bbase) + offB[np] + ((((uint32_t)(g0 + selB)) ^ swB4[np]) << 4));\
        _Pragma("unroll")                                                             \
        for (int mt = 0; mt < 4; ++mt)                                                \
            _Pragma("unroll")                                                         \
            for (int nt = 0; nt < 8; ++nt) {                                          \
                const int np = nt >> 1, lo = (nt & 1) * 2;                            \
                mma_f16(acc[mt][nt][0], acc[mt][nt][1], acc[mt][nt][2], acc[mt][nt][3],\
                        a[mt][0], a[mt][1], a[mt][2], a[mt][3], b[np][lo], b[np][lo + 1]);\
            }                                                                         \
    }

#define STAGE_CHUNK(stagebase, srcA, srcB)                                            \
    _Pragma("unroll")                                                                 \
    for (int it = 0; it < 8; ++it) {                                                  \
        int row = it * 16 + srow;                                                     \
        uint32_t wo = (uint32_t)(row * 32 + ((sg ^ (row & 7)) << 2));                 \
        cp16((stagebase) + wo * 4, (srcA) + (size_t)row * srcStrideA);                \
        cp16((stagebase) + (B_OFF_WORDS + wo) * 4, (srcB) + (size_t)row * srcStrideB);\
    }

// ---------------- GEMM1 (fp16, 64x64 warp tile): retrieved = K @ W^T ----------------
__global__ __launch_bounds__(128, 2) void gemm1_f16_kernel(
    const float* __restrict__ V, float* __restrict__ out) {
    extern __shared__ uint32_t sm1[];
    __shared__ float wred[4];
    const uint32_t sb = smem_u32(sm1);

    const int tid = threadIdx.x;
    const int warp = tid >> 5, lane = tid & 31;
    const int t4 = lane >> 2, tm4 = lane & 3;
    const int n0 = blockIdx.x * 128;
    const int m0 = blockIdx.y * 128;
    const int wm = (warp >> 1) * 64;
    const int wn = (warp & 1) * 64;

    float acc[4][8][4];
    #pragma unroll
    for (int i = 0; i < 4; ++i)
        #pragma unroll
        for (int j = 0; j < 8; ++j)
            #pragma unroll
            for (int r = 0; r < 4; ++r) acc[i][j][r] = 0.f;

    FRAG_SETUP();

    const int srow = tid >> 3, sg = tid & 7;
    const size_t srcStrideA = D, srcStrideB = D;
    const __half* gA = g_k_h + (size_t)m0 * D + sg * 8;
    const __half* gB = g_w_h + (size_t)n0 * D + sg * 8;

    #pragma unroll
    for (int s = 0; s < 2; ++s) {
        STAGE_CHUNK(sb + s * (STAGE_WORDS * 4), gA + s * 64, gB + s * 64);
        CP_COMMIT();
    }

    const int NCH = D / 64;   // 16 chunks
    for (int c = 0; c < NCH; ++c) {
        const int buf = c % 3;
        CP_WAIT1();
        __syncthreads();
        if (c + 2 < NCH) {
            const int nb = (c + 2) % 3;
            STAGE_CHUNK(sb + nb * (STAGE_WORDS * 4), gA + (c + 2) * 64, gB + (c + 2) * 64);
        }
        CP_COMMIT();

        const uint32_t abase = sb + buf * (STAGE_WORDS * 4);
        const uint32_t bbase = abase + B_OFF_WORDS * 4;
        CHUNK_COMPUTE(abase, bbase);
    }

    // ---- Epilogue ----
    CP_WAIT0();
    __syncthreads();   // pipeline smem free; reuse for diff repack

    float lsum = 0.f;
    #pragma unroll
    for (int mt = 0; mt < 4; ++mt) {
        #pragma unroll
        for (int nt = 0; nt < 8; ++nt) {
            int r   = wm + mt * 16 + t4;
            int ccl = wn + nt * 8 + 2 * tm4;
            int rg = m0 + r, cg = n0 + ccl;
            size_t e0 = (size_t)rg * D + cg;
            size_t e1 = (size_t)(rg + 8) * D + cg;
            float2 v0 = *(const float2*)(V + e0);
            float2 v1 = *(const float2*)(V + e1);
            float2 c0 = make_float2(acc[mt][nt][0], acc[mt][nt][1]);
            float2 c1 = make_float2(acc[mt][nt][2], acc[mt][nt][3]);
            *(float2*)(out + RET_OFF + e0) = c0;
            *(float2*)(out + RET_OFF + e1) = c1;
            float d0 = c0.x - v0.x, d1 = c0.y - v0.y;
            float d2 = c1.x - v1.x, d3 = c1.y - v1.y;
            int wrow = ccl >> 1;
            sm1[wrow * 136 + r]     = pack_half(d0, d1);
            sm1[wrow * 136 + r + 8] = pack_half(d2, d3);
            lsum += d0 * d0 + d1 * d1 + d2 * d2 + d3 * d3;
        }
    }
    #pragma unroll
    for (int o = 16; o > 0; o >>= 1) lsum += __shfl_xor_sync(0xffffffffu, lsum, o);
    if (lane == 0) wred[warp] = lsum;
    __syncthreads();

    for (int row = warp; row < 128; row += 4) {
        uint4 w = *(uint4*)&sm1[(row >> 1) * 136 + lane * 4];
        uint32_t sel = (row & 1) ? 0x7632u : 0x5410u;
        uint32_t lo = __byte_perm(w.x, w.y, sel);
        uint32_t hi = __byte_perm(w.z, w.w, sel);
        *(uint2*)&g_diffT_h[(size_t)(n0 + row) * BROWS + m0 + lane * 4] = make_uint2(lo, hi);
    }

    if (tid == 0)
        g_loss_part[blockIdx.y * 8 + blockIdx.x] = wred[0] + wred[1] + wred[2] + wred[3];
}

// ---------------- GEMM2 (fp16, 64x64 warp tile): grad_part[z] = diffT @ kT^T ----------------
__global__ __launch_bounds__(128, 2) void gemm2_f16_kernel() {
    extern __shared__ uint32_t sm2[];
    const uint32_t sb = smem_u32(sm2);

    const int tid = threadIdx.x;
    const int warp = tid >> 5, lane = tid & 31;
    const int t4 = lane >> 2, tm4 = lane & 3;
    const int j0 = blockIdx.x * 128;
    const int i0 = blockIdx.y * 128;
    const int z  = blockIdx.z;
    const int b0z = z * (BROWS / NZ);
    const int wm = (warp >> 1) * 64;   // i
    const int wn = (warp & 1) * 64;    // j

    float acc[4][8][4];
    #pragma unroll
    for (int i = 0; i < 4; ++i)
        #pragma unroll
        for (int j = 0; j < 8; ++j)
            #pragma unroll
            for (int r = 0; r < 4; ++r) acc[i][j][r] = 0.f;

    FRAG_SETUP();

    const int srow = tid >> 3, sg = tid & 7;
    const size_t srcStrideA = BROWS, srcStrideB = BROWS;
    const __half* gA = g_diffT_h + (size_t)i0 * BROWS + b0z + sg * 8;
    const __half* gB = g_kT_h    + (size_t)j0 * BROWS + b0z + sg * 8;

    #pragma unroll
    for (int s = 0; s < 2; ++s) {
        STAGE_CHUNK(sb + s * (STAGE_WORDS * 4), gA + s * 64, gB + s * 64);
        CP_COMMIT();
    }

    const int NCH = (BROWS / NZ) / 64;   // 64 chunks
    for (int c = 0; c < NCH; ++c) {
        const int buf = c % 3;
        CP_WAIT1();
        __syncthreads();
        if (c + 2 < NCH) {
            const int nb = (c + 2) % 3;
            STAGE_CHUNK(sb + nb * (STAGE_WORDS * 4), gA + (c + 2) * 64, gB + (c + 2) * 64);
        }
        CP_COMMIT();

        const uint32_t abase = sb + buf * (STAGE_WORDS * 4);
        const uint32_t bbase = abase + B_OFF_WORDS * 4;
        CHUNK_COMPUTE(abase, bbase);
    }

    float* gp = g_grad_part[z];
    #pragma unroll
    for (int mt = 0; mt < 4; ++mt) {
        #pragma unroll
        for (int nt = 0; nt < 8; ++nt) {
            int r  = i0 + wm + mt * 16 + t4;
            int cc = j0 + wn + nt * 8 + 2 * tm4;
            *(float2*)(gp + (size_t)r * D + cc)       = make_float2(acc[mt][nt][0], acc[mt][nt][1]);
            *(float2*)(gp + (size_t)(r + 8) * D + cc) = make_float2(acc[mt][nt][2], acc[mt][nt][3]);
        }
    }
}

// ---------------- fused update: loss + momentum + norm + weight + norm + final ----------------
// float4 loads for MLP (inputs aligned); scalar stores (NM/W offsets odd).
__global__ __launch_bounds__(256) void fused_update_kernel(
    const float* __restrict__ MOM, const float* __restrict__ MW, float* __restrict__ out) {
    __shared__ float red[256];
    __shared__ int amLast;
    const int tid = threadIdx.x;
    const int t = blockIdx.x * 256 + tid;

    if (blockIdx.x == 0) {   // loss reduce
        float ls = g_loss_part[tid] + g_loss_part[tid + 256] +
                   g_loss_part[tid + 512] + g_loss_part[tid + 768];
        red[tid] = ls;
        __syncthreads();
        for (int s = 128; s > 0; s >>= 1) {
            if (tid < s) red[tid] += red[tid + s];
            __syncthreads();
        }
        if (tid == 0) out[LOSS_OFF] = red[0] / (float)(BROWS * D);
        __syncthreads();
    }

    const float eta = g_scalars[1], theta = g_scalars[2];
    const float lr_th = TTT_LR * theta;
    const float one_m_a = 1.0f - g_scalars[0];

    // Phase 1: nm in registers + norm partial (float4 loads; 4 iters x 4 elems)
    float nm[16];
    float nsum = 0.f;
    #pragma unroll
    for (int it = 0; it < 4; ++it) {
        int e4 = t + it * 65536;            // float4 index
        float4 g4 = *(const float4*)(&g_grad_part[0][e4 * 4]);
        #pragma unroll
        for (int z = 1; z < NZ; ++z) {
            float4 p = *(const float4*)(&g_grad_part[z][e4 * 4]);
            g4.x += p.x; g4.y += p.y; g4.z += p.z; g4.w += p.w;
        }
        float4 m4 = *(const float4*)(MOM + e4 * 4);
        float gv[4] = { g4.x, g4.y, g4.z, g4.w };
        float mv[4] = { m4.x, m4.y, m4.z, m4.w };
        #pragma unroll
        for (int q = 0; q < 4; ++q) {
            float g = gv[q] * TWO_OVER_N;
            float gc = fminf(1.0f, fmaxf(-1.0f, g));
            float v = eta * mv[q] - lr_th * gc;
            nm[it * 4 + q] = v;
            nsum += v * v;
        }
    }
    red[tid] = nsum;
    __syncthreads();
    for (int s = 128; s > 0; s >>= 1) {
        if (tid < s) red[tid] += red[tid + s];
        __syncthreads();
    }
    if (tid == 0) {
        g_norm_part[0][blockIdx.x] = red[0];
        __threadfence();
        amLast = (atomicAdd((int*)&g_ctr[0], 1) == 255);
    }
    __syncthreads();
    if (amLast) {
        red[tid] = g_norm_part[0][tid];
        __syncthreads();
        for (int s = 128; s > 0; s >>= 1) {
            if (tid < s) red[tid] += red[tid + s];
            __syncthreads();
        }
        if (tid == 0) {
            float n = sqrtf(red[0]);
            g_scalars[4] = (n > MEM_MAX_NORM) ? (MEM_MAX_NORM / (n + 1e-8f)) : 1.0f;
            __threadfence();
            g_ctr[0] = -1;
        }
    }
    if (tid == 0) { while (g_ctr[0] >= 0) { } }
    __syncthreads();
    __threadfence();
    const float sm_ = g_scalars[4];

    // Phase 2: nm output, w in registers + norm partial
    float w[16];
    float wsum = 0.f;
    #pragma unroll
    for (int it = 0; it < 4; ++it) {
        int e4 = t + it * 65536;
        float4 mw4 = *(const float4*)(MW + e4 * 4);
        float mwv[4] = { mw4.x, mw4.y, mw4.z, mw4.w };
        #pragma unroll
        for (int q = 0; q < 4; ++q) {
            float nmv = nm[it * 4 + q] * sm_;
            out[NM_OFF + e4 * 4 + q] = nmv;        // odd offset -> scalar store
            float wv = one_m_a * mwv[q] + nmv;
            w[it * 4 + q] = wv;
            wsum += wv * wv;
        }
    }
    red[tid] = wsum;
    __syncthreads();
    for (int s = 128; s > 0; s >>= 1) {
        if (tid < s) red[tid] += red[tid + s];
        __syncthreads();
    }
    if (tid == 0) {
        g_norm_part[1][blockIdx.x] = red[0];
        __threadfence();
        amLast = (atomicAdd((int*)&g_ctr[1], 1) == 255);
    }
    __syncthreads();
    if (amLast) {
        red[tid] = g_norm_part[1][tid];
        __syncthreads();
        for (int s = 128; s > 0; s >>= 1) {
            if (tid < s) red[tid] += red[tid + s];
            __syncthreads();
        }
        if (tid == 0) {
            float n = sqrtf(red[0]);
            g_scalars[5] = (n > MEM_MAX_NORM) ? (MEM_MAX_NORM / (n + 1e-8f)) : 1.0f;
            __threadfence();
            g_ctr[1] = -1;
        }
    }
    if (tid == 0) { while (g_ctr[1] >= 0) { } }
    __syncthreads();
    __threadfence();
    const float sw = g_scalars[5];

    #pragma unroll
    for (int it = 0; it < 4; ++it) {
        int e4 = t + it * 65536;
        #pragma unroll
        for (int q = 0; q < 4; ++q)
            out[W_OFF + e4 * 4 + q] = w[it * 4 + q] * sw;   // odd offset -> scalar store
    }
}

// ---------------- launch ----------------
extern "C" void kernel_launch(void* const* d_in, const int* in_sizes, int n_in,
                              void* d_out, int out_size) {
    const float* k    = (const float*)d_in[0];
    const float* v    = (const float*)d_in[1];
    const float* memw = (const float*)d_in[2];
    const float* gw   = (const float*)d_in[3];
    const float* gb   = (const float*)d_in[4];
    const float* mom  = (const float*)d_in[5];
    float* out = (float*)d_out;

    const int g_smem = 3 * STAGE_WORDS * 4;   // 98304
    cudaFuncSetAttribute(gemm1_f16_kernel, cudaFuncAttributeMaxDynamicSharedMemorySize, g_smem);
    cudaFuncSetAttribute(gemm2_f16_kernel, cudaFuncAttributeMaxDynamicSharedMemorySize, g_smem);

    colsum_prep_kernel<<<dim3(8, 129), 256>>>(k, memw);
    kagg_gates_kernel<<<1, 1024>>>(gw, gb, out);
    gemm1_f16_kernel<<<dim3(8, 128), 128, g_smem>>>(v, out);
    gemm2_f16_kernel<<<dim3(8, 8, NZ), 128, g_smem>>>();   // launch #4 -> ncu capture
    fused_update_kernel<<<256, 256>>>(mom, memw, out);
}

// round 17
// speedup vs baseline: 1.1997x; 1.0355x over previous
#include <cuda_runtime.h>
#include <cuda_fp16.h>
#include <math.h>
#include <stdint.h>

// Problem constants
#define BROWS 16384
#define D     1024

// Output layout: retrieved (B*D) | loss (1) | new_weight (D*D) | new_momentum (D*D) | gates (3)
#define RET_OFF   0
#define LOSS_OFF  (BROWS * D)
#define W_OFF     (LOSS_OFF + 1)              // odd -> scalar stores only
#define NM_OFF    (W_OFF + D * D)             // odd -> scalar stores only
#define GATES_OFF (NM_OFF + D * D)

#define MEM_MAX_NORM 5.0f
#define TTT_LR 0.005f
#define TWO_OVER_N (2.0f / (float)(BROWS * D))

#define NZ 4   // gemm2 split-B slices (proven best)

// ---------------- device scratch (static, no runtime allocation) ----------------
__device__ float g_kagg_part[128][D];
__device__ float g_scalars[8];        // 0:alpha 1:eta 2:theta 4:scale_m 5:scale_w
__device__ float g_loss_part[1024];
__device__ float g_grad_part[NZ][D * D];  // split-B partials for GEMM2 (16 MB)
__device__ float g_norm_part[2][256];
__device__ volatile int g_ctr[2];         // 0..255 counting; -1 = scale ready
__device__ __half g_w_h[D * D];            // fp16 W, row-major [n][k] (2 MB)
__device__ __half g_kT_h[D * BROWS];       // fp16 K^T [c][b] (32 MB)
__device__ __half g_diffT_h[D * BROWS];    // fp16 (retrieved-V)^T [i][b] (32 MB)

// ================= PTX helpers (family-portable, sm_80+) =================
__device__ __forceinline__ uint32_t pack_half(float a, float b) {
    __half2 h = __floats2half2_rn(a, b);
    return *(uint32_t*)&h;
}
__device__ __forceinline__ void mma_f16(float& c0, float& c1, float& c2, float& c3,
                                        uint32_t a0, uint32_t a1, uint32_t a2, uint32_t a3,
                                        uint32_t b0, uint32_t b1) {
    asm volatile(
        "mma.sync.aligned.m16n8k16.row.col.f32.f16.f16.f32 "
        "{%0,%1,%2,%3}, {%4,%5,%6,%7}, {%8,%9}, {%0,%1,%2,%3};"
        : "+f"(c0), "+f"(c1), "+f"(c2), "+f"(c3)
        : "r"(a0), "r"(a1), "r"(a2), "r"(a3), "r"(b0), "r"(b1));
}
__device__ __forceinline__ void ldsm_x4(uint32_t& r0, uint32_t& r1, uint32_t& r2, uint32_t& r3,
                                        uint32_t addr) {
    asm volatile("ldmatrix.sync.aligned.m8n8.x4.shared.b16 {%0,%1,%2,%3}, [%4];"
                 : "=r"(r0), "=r"(r1), "=r"(r2), "=r"(r3) : "r"(addr));
}
__device__ __forceinline__ void ldsm_x4_t(uint32_t& r0, uint32_t& r1, uint32_t& r2, uint32_t& r3,
                                          uint32_t addr) {
    asm volatile("ldmatrix.sync.aligned.m8n8.x4.trans.shared.b16 {%0,%1,%2,%3}, [%4];"
                 : "=r"(r0), "=r"(r1), "=r"(r2), "=r"(r3) : "r"(addr));
}
__device__ __forceinline__ uint32_t smem_u32(const void* p) {
    uint32_t a;
    asm("{ .reg .u64 t; cvta.to.shared.u64 t, %1; cvt.u32.u64 %0, t; }" : "=r"(a) : "l"(p));
    return a;
}
__device__ __forceinline__ void cp16(uint32_t dst, const void* src) {
    asm volatile("cp.async.cg.shared.global [%0], [%1], 16;" :: "r"(dst), "l"(src));
}
#define CP_COMMIT() asm volatile("cp.async.commit_group;" ::: "memory")
#define CP_WAIT1()  asm volatile("cp.async.wait_group 1;" ::: "memory")
#define CP_WAIT0()  asm volatile("cp.async.wait_group 0;" ::: "memory")

// stage = A(16KB) + B(16KB) = 32KB = 8192 words
#define STAGE_WORDS 8192
#define B_OFF_WORDS 4096

// ---------------- colsum + fp16 K^T + fp16(W) (fused prep; no k_h) ----------------
__global__ __launch_bounds__(256) void colsum_prep_kernel(const float* __restrict__ K,
                                                          const float* __restrict__ W) {
    if (blockIdx.y == 128) {   // W conversion blocks
        int base = (blockIdx.x * 256 + threadIdx.x) * 2;
        #pragma unroll
        for (int it = 0; it < 256; ++it) {
            int e = base + it * 4096;
            float2 w2 = *(const float2*)(W + e);
            *(uint32_t*)(&g_w_h[e]) = pack_half(w2.x, w2.y);
        }
        return;
    }
    __shared__ uint32_t st[128 * 64];
    __shared__ float red2[256];
    const int t  = threadIdx.x;
    const int cl = t & 127, rq = t >> 7;
    const int c  = blockIdx.x * 128 + cl;
    const int r0 = blockIdx.y * 128;

    float s = 0.f, prev = 0.f;
    #pragma unroll 8
    for (int i = 0; i < 64; ++i) {
        int r = r0 + rq * 64 + i;
        float kv = K[(size_t)r * D + c];
        s += kv;
        if (i & 1) {
            int r2 = rq * 32 + (i >> 1);
            st[cl * 64 + (r2 ^ (cl & 31))] = pack_half(prev, kv);
        } else prev = kv;
    }
    red2[t] = s;
    __syncthreads();
    if (t < 128) g_kagg_part[blockIdx.y][blockIdx.x * 128 + t] = red2[t] + red2[t + 128];

    uint32_t* kTw = (uint32_t*)g_kT_h;
    size_t dstbase = ((size_t)(blockIdx.x * 128 + cl) * BROWS + r0) / 2 + rq * 32;
    #pragma unroll
    for (int q4 = 0; q4 < 32; q4 += 4) {
        uint4 vv;
        vv.x = st[cl * 64 + ((rq * 32 + q4 + 0) ^ (cl & 31))];
        vv.y = st[cl * 64 + ((rq * 32 + q4 + 1) ^ (cl & 31))];
        vv.z = st[cl * 64 + ((rq * 32 + q4 + 2) ^ (cl & 31))];
        vv.w = st[cl * 64 + ((rq * 32 + q4 + 3) ^ (cl & 31))];
        *(uint4*)(kTw + dstbase + q4) = vv;
    }
}

// ---------------- fused kagg + gates (+ counter reset for graph replay) ----------------
__global__ void kagg_gates_kernel(const float* __restrict__ GW, const float* __restrict__ GB,
                                  float* __restrict__ out) {
    __shared__ float red[1024];
    __shared__ float kag[1024];
    int t = threadIdx.x;
    if (t == 0) { g_ctr[0] = 0; g_ctr[1] = 0; }
    float s = 0.f;
    #pragma unroll 8
    for (int p = 0; p < 128; ++p) s += g_kagg_part[p][t];
    kag[t] = s * (1.0f / (float)BROWS);
    __syncthreads();
    for (int g = 0; g < 3; ++g) {
        red[t] = kag[t] * GW[g * D + t];
        __syncthreads();
        for (int st = 512; st > 0; st >>= 1) {
            if (t < st) red[t] += red[t + st];
            __syncthreads();
        }
        if (t == 0) {
            float z  = red[0] + GB[g];
            float sg = 1.0f / (1.0f + expf(-z));
            g_scalars[g] = sg;
            out[GATES_OFF + g] = sg;
        }
        __syncthreads();
    }
}

// ---------------- GEMM1 (fp16, 64x64 warp tile, trans-A from kT): retrieved = K @ W^T ----------------
__global__ __launch_bounds__(128, 2) void gemm1_f16_kernel(
    const float* __restrict__ V, float* __restrict__ out) {
    extern __shared__ uint32_t sm1[];
    __shared__ float wred[4];
    const uint32_t sb = smem_u32(sm1);

    const int tid = threadIdx.x;
    const int warp = tid >> 5, lane = tid & 31;
    const int t4 = lane >> 2, tm4 = lane & 3;
    const int n0 = blockIdx.x * 128;
    const int m0 = blockIdx.y * 128;
    const int wm = (warp >> 1) * 64;
    const int wn = (warp & 1) * 64;

    float acc[4][8][4];
    #pragma unroll
    for (int i = 0; i < 4; ++i)
        #pragma unroll
        for (int j = 0; j < 8; ++j)
            #pragma unroll
            for (int r = 0; r < 4; ++r) acc[i][j][r] = 0.f;

    // A fragment selectors (trans path): stage A = 64 k-rows x 256B (128 m-halves)
    const int laneK   = (lane & 7) | ((lane & 16) >> 1);  // 0..15
    const int colOffA = ((lane >> 3) & 1) << 3;           // 0/8
    uint32_t offA[4];
    #pragma unroll
    for (int mt = 0; mt < 4; ++mt) {
        int g = (wm + mt * 16 + colOffA) >> 3;            // m-granule (16B)
        offA[mt] = (uint32_t)(laneK * 256 + ((g ^ (laneK & 7)) << 4));
    }
    // B fragment selectors (row-major n x k)
    const int laneRowB = (lane & 7) | ((lane & 16) >> 1);
    const int selB = (lane >> 3) & 1;
    uint32_t offB[4], swB4[4];
    #pragma unroll
    for (int np = 0; np < 4; ++np) {
        int row = wn + np * 16 + laneRowB;
        offB[np] = row * 128;
        swB4[np] = row & 7;
    }

    // staging maps
    const int rA = tid >> 4, gAq = tid & 15;   // A: 8 passes x 8 rows, 16 granules/row
    const int rB = tid >> 3, gBq = tid & 7;    // B: 8 passes x 16 rows, 8 granules/row
    const __half* gAbase = g_kT_h + m0;                 // rows = k, cols = m (b)
    const __half* gBbase = g_w_h + (size_t)n0 * D;

    #pragma unroll
    for (int s = 0; s < 2; ++s) {
        #pragma unroll
        for (int it = 0; it < 8; ++it) {
            int rowA = it * 8 + rA;
            uint32_t dA = sb + s * (STAGE_WORDS * 4) + rowA * 256 + (((uint32_t)(gAq ^ (rowA & 7))) << 4);
            cp16(dA, gAbase + (size_t)(s * 64 + rowA) * BROWS + gAq * 8);
            int rowB = it * 16 + rB;
            uint32_t dB = sb + s * (STAGE_WORDS * 4) + B_OFF_WORDS * 4 + rowB * 128 + (((uint32_t)(gBq ^ (rowB & 7))) << 4);
            cp16(dB, gBbase + (size_t)rowB * D + s * 64 + gBq * 8);
        }
        CP_COMMIT();
    }

    const int NCH = D / 64;   // 16 chunks
    for (int c = 0; c < NCH; ++c) {
        const int buf = c % 3;
        CP_WAIT1();
        __syncthreads();
        if (c + 2 < NCH) {
            const int nb = (c + 2) % 3;
            #pragma unroll
            for (int it = 0; it < 8; ++it) {
                int rowA = it * 8 + rA;
                uint32_t dA = sb + nb * (STAGE_WORDS * 4) + rowA * 256 + (((uint32_t)(gAq ^ (rowA & 7))) << 4);
                cp16(dA, gAbase + (size_t)((c + 2) * 64 + rowA) * BROWS + gAq * 8);
                int rowB = it * 16 + rB;
                uint32_t dB = sb + nb * (STAGE_WORDS * 4) + B_OFF_WORDS * 4 + rowB * 128 + (((uint32_t)(gBq ^ (rowB & 7))) << 4);
                cp16(dB, gBbase + (size_t)rowB * D + (c + 2) * 64 + gBq * 8);
            }
        }
        CP_COMMIT();

        const uint32_t abase = sb + buf * (STAGE_WORDS * 4);
        const uint32_t bbase = abase + B_OFF_WORDS * 4;
        #pragma unroll
        for (int ks = 0; ks < 4; ++ks) {
            const int g0 = ks * 2;
            uint32_t a[4][4], b[4][4];
            #pragma unroll
            for (int mt = 0; mt < 4; ++mt)
                ldsm_x4_t(a[mt][0], a[mt][1], a[mt][2], a[mt][3],
                          abase + ks * 4096 + offA[mt]);
            #pragma unroll
            for (int np = 0; np < 4; ++np)
                ldsm_x4(b[np][0], b[np][1], b[np][2], b[np][3],
                        bbase + offB[np] + ((((uint32_t)(g0 + selB)) ^ swB4[np]) << 4));
            #pragma unroll
            for (int mt = 0; mt < 4; ++mt)
                #pragma unroll
                for (int nt = 0; nt < 8; ++nt) {
                    const int np = nt >> 1, lo = (nt & 1) * 2;
                    mma_f16(acc[mt][nt][0], acc[mt][nt][1], acc[mt][nt][2], acc[mt][nt][3],
                            a[mt][0], a[mt][1], a[mt][2], a[mt][3], b[np][lo], b[np][lo + 1]);
                }
        }
    }

    // ---- Epilogue ----
    CP_WAIT0();
    __syncthreads();   // pipeline smem free; reuse for diff repack

    float lsum = 0.f;
    #pragma unroll
    for (int mt = 0; mt < 4; ++mt) {
        #pragma unroll
        for (int nt = 0; nt < 8; ++nt) {
            int r   = wm + mt * 16 + t4;
            int ccl = wn + nt * 8 + 2 * tm4;
            int rg = m0 + r, cg = n0 + ccl;
            size_t e0 = (size_t)rg * D + cg;
            size_t e1 = (size_t)(rg + 8) * D + cg;
            float2 v0 = *(const float2*)(V + e0);
            float2 v1 = *(const float2*)(V + e1);
            float2 c0 = make_float2(acc[mt][nt][0], acc[mt][nt][1]);
            float2 c1 = make_float2(acc[mt][nt][2], acc[mt][nt][3]);
            *(float2*)(out + RET_OFF + e0) = c0;
            *(float2*)(out + RET_OFF + e1) = c1;
            float d0 = c0.x - v0.x, d1 = c0.y - v0.y;
            float d2 = c1.x - v1.x, d3 = c1.y - v1.y;
            int wrow = ccl >> 1;
            sm1[wrow * 136 + r]     = pack_half(d0, d1);
            sm1[wrow * 136 + r + 8] = pack_half(d2, d3);
            lsum += d0 * d0 + d1 * d1 + d2 * d2 + d3 * d3;
        }
    }
    #pragma unroll
    for (int o = 16; o > 0; o >>= 1) lsum += __shfl_xor_sync(0xffffffffu, lsum, o);
    if (lane == 0) wred[warp] = lsum;
    __syncthreads();

    for (int row = warp; row < 128; row += 4) {
        uint4 w = *(uint4*)&sm1[(row >> 1) * 136 + lane * 4];
        uint32_t sel = (row & 1) ? 0x7632u : 0x5410u;
        uint32_t lo = __byte_perm(w.x, w.y, sel);
        uint32_t hi = __byte_perm(w.z, w.w, sel);
        *(uint2*)&g_diffT_h[(size_t)(n0 + row) * BROWS + m0 + lane * 4] = make_uint2(lo, hi);
    }

    if (tid == 0)
        g_loss_part[blockIdx.y * 8 + blockIdx.x] = wred[0] + wred[1] + wred[2] + wred[3];
}

// ---------------- GEMM2 (fp16, 64x64 warp tile): grad_part[z] = diffT @ kT^T ----------------
__global__ __launch_bounds__(128, 2) void gemm2_f16_kernel() {
    extern __shared__ uint32_t sm2[];
    const uint32_t sb = smem_u32(sm2);

    const int tid = threadIdx.x;
    const int warp = tid >> 5, lane = tid & 31;
    const int t4 = lane >> 2, tm4 = lane & 3;
    const int j0 = blockIdx.x * 128;
    const int i0 = blockIdx.y * 128;
    const int z  = blockIdx.z;
    const int b0z = z * (BROWS / NZ);
    const int wm = (warp >> 1) * 64;   // i
    const int wn = (warp & 1) * 64;    // j

    float acc[4][8][4];
    #pragma unroll
    for (int i = 0; i < 4; ++i)
        #pragma unroll
        for (int j = 0; j < 8; ++j)
            #pragma unroll
            for (int r = 0; r < 4; ++r) acc[i][j][r] = 0.f;

    const int laneRowA = (lane & 7) | (lane & 8);
    const int selA = lane >> 4;
    const int laneRowB = (lane & 7) | ((lane & 16) >> 1);
    const int selB = (lane >> 3) & 1;
    uint32_t offA[4], swA4[4];
    #pragma unroll
    for (int mt = 0; mt < 4; ++mt) {
        int row = wm + mt * 16 + laneRowA;
        offA[mt] = row * 128;
        swA4[mt] = row & 7;
    }
    uint32_t offB[4], swB4[4];
    #pragma unroll
    for (int np = 0; np < 4; ++np) {
        int row = wn + np * 16 + laneRowB;
        offB[np] = row * 128;
        swB4[np] = row & 7;
    }

    const int srow = tid >> 3, sg = tid & 7;
    const __half* gA = g_diffT_h + (size_t)i0 * BROWS + b0z + sg * 8;
    const __half* gB = g_kT_h    + (size_t)j0 * BROWS + b0z + sg * 8;

    #pragma unroll
    for (int s = 0; s < 2; ++s) {
        #pragma unroll
        for (int it = 0; it < 8; ++it) {
            int row = it * 16 + srow;
            uint32_t wo = (uint32_t)(row * 32 + ((sg ^ (row & 7)) << 2));
            cp16(sb + s * (STAGE_WORDS * 4) + wo * 4, gA + (size_t)row * BROWS + s * 64);
            cp16(sb + s * (STAGE_WORDS * 4) + (B_OFF_WORDS + wo) * 4, gB + (size_t)row * BROWS + s * 64);
        }
        CP_COMMIT();
    }

    const int NCH = (BROWS / NZ) / 64;   // 64 chunks
    for (int c = 0; c < NCH; ++c) {
        const int buf = c % 3;
        CP_WAIT1();
        __syncthreads();
        if (c + 2 < NCH) {
            const int nb = (c + 2) % 3;
            #pragma unroll
            for (int it = 0; it < 8; ++it) {
                int row = it * 16 + srow;
                uint32_t wo = (uint32_t)(row * 32 + ((sg ^ (row & 7)) << 2));
                cp16(sb + nb * (STAGE_WORDS * 4) + wo * 4, gA + (size_t)row * BROWS + (c + 2) * 64);
                cp16(sb + nb * (STAGE_WORDS * 4) + (B_OFF_WORDS + wo) * 4, gB + (size_t)row * BROWS + (c + 2) * 64);
            }
        }
        CP_COMMIT();

        const uint32_t abase = sb + buf * (STAGE_WORDS * 4);
        const uint32_t bbase = abase + B_OFF_WORDS * 4;
        #pragma unroll
        for (int ks = 0; ks < 4; ++ks) {
            const int g0 = ks * 2;
            uint32_t a[4][4], b[4][4];
            #pragma unroll
            for (int mt = 0; mt < 4; ++mt)
                ldsm_x4(a[mt][0], a[mt][1], a[mt][2], a[mt][3],
                        abase + offA[mt] + ((((uint32_t)(g0 + selA)) ^ swA4[mt]) << 4));
            #pragma unroll
            for (int np = 0; np < 4; ++np)
                ldsm_x4(b[np][0], b[np][1], b[np][2], b[np][3],
                        bbase + offB[np] + ((((uint32_t)(g0 + selB)) ^ swB4[np]) << 4));
            #pragma unroll
            for (int mt = 0; mt < 4; ++mt)
                #pragma unroll
                for (int nt = 0; nt < 8; ++nt) {
                    const int np = nt >> 1, lo = (nt & 1) * 2;
                    mma_f16(acc[mt][nt][0], acc[mt][nt][1], acc[mt][nt][2], acc[mt][nt][3],
                            a[mt][0], a[mt][1], a[mt][2], a[mt][3], b[np][lo], b[np][lo + 1]);
                }
        }
    }

    float* gp = g_grad_part[z];
    #pragma unroll
    for (int mt = 0; mt < 4; ++mt) {
        #pragma unroll
        for (int nt = 0; nt < 8; ++nt) {
            int r  = i0 + wm + mt * 16 + t4;
            int cc = j0 + wn + nt * 8 + 2 * tm4;
            *(float2*)(gp + (size_t)r * D + cc)       = make_float2(acc[mt][nt][0], acc[mt][nt][1]);
            *(float2*)(gp + (size_t)(r + 8) * D + cc) = make_float2(acc[mt][nt][2], acc[mt][nt][3]);
        }
    }
}

// ---------------- fused update: loss + momentum + norm + weight + norm + final ----------------
__global__ __launch_bounds__(256) void fused_update_kernel(
    const float* __restrict__ MOM, const float* __restrict__ MW, float* __restrict__ out) {
    __shared__ float red[256];
    __shared__ int amLast;
    const int tid = threadIdx.x;
    const int t = blockIdx.x * 256 + tid;

    if (blockIdx.x == 0) {   // loss reduce
        float ls = g_loss_part[tid] + g_loss_part[tid + 256] +
                   g_loss_part[tid + 512] + g_loss_part[tid + 768];
        red[tid] = ls;
        __syncthreads();
        for (int s = 128; s > 0; s >>= 1) {
            if (tid < s) red[tid] += red[tid + s];
            __syncthreads();
        }
        if (tid == 0) out[LOSS_OFF] = red[0] / (float)(BROWS * D);
        __syncthreads();
    }

    const float eta = g_scalars[1], theta = g_scalars[2];
    const float lr_th = TTT_LR * theta;
    const float one_m_a = 1.0f - g_scalars[0];

    // Phase 1: nm in registers + norm partial (float4 loads)
    float nm[16];
    float nsum = 0.f;
    #pragma unroll
    for (int it = 0; it < 4; ++it) {
        int e4 = t + it * 65536;
        float4 g4 = *(const float4*)(&g_grad_part[0][e4 * 4]);
        #pragma unroll
        for (int z = 1; z < NZ; ++z) {
            float4 p = *(const float4*)(&g_grad_part[z][e4 * 4]);
            g4.x += p.x; g4.y += p.y; g4.z += p.z; g4.w += p.w;
        }
        float4 m4 = *(const float4*)(MOM + e4 * 4);
        float gv[4] = { g4.x, g4.y, g4.z, g4.w };
        float mv[4] = { m4.x, m4.y, m4.z, m4.w };
        #pragma unroll
        for (int q = 0; q < 4; ++q) {
            float g = gv[q] * TWO_OVER_N;
            float gc = fminf(1.0f, fmaxf(-1.0f, g));
            float v = eta * mv[q] - lr_th * gc;
            nm[it * 4 + q] = v;
            nsum += v * v;
        }
    }
    red[tid] = nsum;
    __syncthreads();
    for (int s = 128; s > 0; s >>= 1) {
        if (tid < s) red[tid] += red[tid + s];
        __syncthreads();
    }
    if (tid == 0) {
        g_norm_part[0][blockIdx.x] = red[0];
        __threadfence();
        amLast = (atomicAdd((int*)&g_ctr[0], 1) == 255);
    }
    __syncthreads();
    if (amLast) {
        red[tid] = g_norm_part[0][tid];
        __syncthreads();
        for (int s = 128; s > 0; s >>= 1) {
            if (tid < s) red[tid] += red[tid + s];
            __syncthreads();
        }
        if (tid == 0) {
            float n = sqrtf(red[0]);
            g_scalars[4] = (n > MEM_MAX_NORM) ? (MEM_MAX_NORM / (n + 1e-8f)) : 1.0f;
            __threadfence();
            g_ctr[0] = -1;
        }
    }
    if (tid == 0) { while (g_ctr[0] >= 0) { } }
    __syncthreads();
    __threadfence();
    const float sm_ = g_scalars[4];

    // Phase 2: nm output, w in registers + norm partial
    float w[16];
    float wsum = 0.f;
    #pragma unroll
    for (int it = 0; it < 4; ++it) {
        int e4 = t + it * 65536;
        float4 mw4 = *(const float4*)(MW + e4 * 4);
        float mwv[4] = { mw4.x, mw4.y, mw4.z, mw4.w };
        #pragma unroll
        for (int q = 0; q < 4; ++q) {
            float nmv = nm[it * 4 + q] * sm_;
            out[NM_OFF + e4 * 4 + q] = nmv;
            float wv = one_m_a * mwv[q] + nmv;
            w[it * 4 + q] = wv;
            wsum += wv * wv;
        }
    }
    red[tid] = wsum;
    __syncthreads();
    for (int s = 128; s > 0; s >>= 1) {
        if (tid < s) red[tid] += red[tid + s];
        __syncthreads();
    }
    if (tid == 0) {
        g_norm_part[1][blockIdx.x] = red[0];
        __threadfence();
        amLast = (atomicAdd((int*)&g_ctr[1], 1) == 255);
    }
    __syncthreads();
    if (amLast) {
        red[tid] = g_norm_part[1][tid];
        __syncthreads();
        for (int s = 128; s > 0; s >>= 1) {
            if (tid < s) red[tid] += red[tid + s];
            __syncthreads();
        }
        if (tid == 0) {
            float n = sqrtf(red[0]);
            g_scalars[5] = (n > MEM_MAX_NORM) ? (MEM_MAX_NORM / (n + 1e-8f)) : 1.0f;
            __threadfence();
            g_ctr[1] = -1;
        }
    }
    if (tid == 0) { while (g_ctr[1] >= 0) { } }
    __syncthreads();
    __threadfence();
    const float sw = g_scalars[5];

    #pragma unroll
    for (int it = 0; it < 4; ++it) {
        int e4 = t + it * 65536;
        #pragma unroll
        for (int q = 0; q < 4; ++q)
            out[W_OFF + e4 * 4 + q] = w[it * 4 + q] * sw;
    }
}

// ---------------- launch ----------------
extern "C" void kernel_launch(void* const* d_in, const int* in_sizes, int n_in,
                              void* d_out, int out_size) {
    const float* k    = (const float*)d_in[0];
    const float* v    = (const float*)d_in[1];
    const float* memw = (const float*)d_in[2];
    const float* gw   = (const float*)d_in[3];
    const float* gb   = (const float*)d_in[4];
    const float* mom  = (const float*)d_in[5];
    float* out = (float*)d_out;

    const int g_smem = 3 * STAGE_WORDS * 4;   // 98304
    cudaFuncSetAttribute(gemm1_f16_kernel, cudaFuncAttributeMaxDynamicSharedMemorySize, g_smem);
    cudaFuncSetAttribute(gemm2_f16_kernel, cudaFuncAttributeMaxDynamicSharedMemorySize, g_smem);

    colsum_prep_kernel<<<dim3(8, 129), 256>>>(k, memw);
    kagg_gates_kernel<<<1, 1024>>>(gw, gb, out);
    gemm1_f16_kernel<<<dim3(8, 128), 128, g_smem>>>(v, out);
    gemm2_f16_kernel<<<dim3(8, 8, NZ), 128, g_smem>>>();   // launch #4 -> ncu capture
    fused_update_kernel<<<256, 256>>>(mom, memw, out);
}